// round 1
// baseline (speedup 1.0000x reference)
#include <cuda_runtime.h>
#include <math.h>

#define OBS 17
#define ACT 4
#define HID 64
#define LOG_2PI 1.8378770664093453f

__device__ float g_Qinv[16];

// ---------------------------------------------------------------------------
// Prep: compute Qinv = (tril(L) tril(L)^T + 1e-4 I)^{-1} once, in double.
// ---------------------------------------------------------------------------
__global__ void qinv_kernel(const float* __restrict__ L) {
    if (threadIdx.x != 0 || blockIdx.x != 0) return;
    double Lt[4][4];
    for (int i = 0; i < 4; i++)
        for (int j = 0; j < 4; j++)
            Lt[i][j] = (j <= i) ? (double)L[i * 4 + j] : 0.0;
    double M[4][8];
    for (int i = 0; i < 4; i++) {
        for (int j = 0; j < 4; j++) {
            double s = (i == j) ? 1e-4 : 0.0;
            for (int k = 0; k < 4; k++) s += Lt[i][k] * Lt[j][k];
            M[i][j] = s;
            M[i][4 + j] = (i == j) ? 1.0 : 0.0;
        }
    }
    for (int c = 0; c < 4; c++) {
        int p = c;
        for (int r = c + 1; r < 4; r++) if (fabs(M[r][c]) > fabs(M[p][c])) p = r;
        if (p != c) for (int j = 0; j < 8; j++) { double t = M[c][j]; M[c][j] = M[p][j]; M[p][j] = t; }
        double inv = 1.0 / M[c][c];
        for (int j = 0; j < 8; j++) M[c][j] *= inv;
        for (int r = 0; r < 4; r++) if (r != c) {
            double f = M[r][c];
            for (int j = 0; j < 8; j++) M[r][j] -= f * M[c][j];
        }
    }
    for (int i = 0; i < 4; i++)
        for (int j = 0; j < 4; j++)
            g_Qinv[i * 4 + j] = (float)M[i][4 + j];
}

// ---------------------------------------------------------------------------
// Main fused kernel: one thread per row.
// ---------------------------------------------------------------------------
__global__ __launch_bounds__(256) void fused_kernel(
    const float* __restrict__ x, const float* __restrict__ sdfs,
    const float* __restrict__ grads, const float* __restrict__ f_x,
    const float* __restrict__ g_x, const float* __restrict__ action,
    const float* __restrict__ cW1, const float* __restrict__ cb1,
    const float* __restrict__ cW2, const float* __restrict__ cb2,
    const float* __restrict__ cW3, const float* __restrict__ cb3,
    const float* __restrict__ aW1, const float* __restrict__ ab1,
    const float* __restrict__ aW2, const float* __restrict__ ab2,
    const float* __restrict__ aW3, const float* __restrict__ ab3,
    const float* __restrict__ logstd, const float* __restrict__ s0,
    float* __restrict__ out, int N)
{
    __shared__ __align__(16) float sAW1[OBS * HID];
    __shared__ __align__(16) float sAW2[HID * HID];
    __shared__ __align__(16) float sAW3[HID * ACT];
    __shared__ __align__(16) float sCW1[OBS * HID];
    __shared__ __align__(16) float sCW2[HID * HID];
    __shared__ __align__(16) float sCW3[HID];
    __shared__ __align__(16) float sAb1[HID], sAb2[HID], sCb1[HID], sCb2[HID];
    __shared__ __align__(16) float sAb3[ACT], sLogstd[ACT], sInvStd[ACT];
    __shared__ __align__(16) float sQinv[16];
    __shared__ __align__(16) float sMisc[4]; // 0: cb3, 1: s0, 2: entropy

    const int tid = threadIdx.x;
    for (int i = tid; i < OBS * HID; i += 256) { sAW1[i] = aW1[i]; sCW1[i] = cW1[i]; }
    for (int i = tid; i < HID * HID; i += 256) { sAW2[i] = aW2[i]; sCW2[i] = cW2[i]; }
    for (int i = tid; i < HID * ACT; i += 256) sAW3[i] = aW3[i];
    if (tid < HID) {
        sAb1[tid] = ab1[tid]; sAb2[tid] = ab2[tid];
        sCb1[tid] = cb1[tid]; sCb2[tid] = cb2[tid];
        sCW3[tid] = cW3[tid];
    }
    if (tid < ACT) {
        float ls = logstd[tid];
        sAb3[tid] = ab3[tid];
        sLogstd[tid] = ls;
        sInvStd[tid] = expf(-ls);
    }
    if (tid < 16) sQinv[tid] = g_Qinv[tid];
    if (tid == 0) {
        sMisc[0] = cb3[0];
        sMisc[1] = s0[0];
        float e = 0.0f;
        for (int a = 0; a < ACT; a++) e += 0.5f + 0.5f * LOG_2PI + logstd[a];
        sMisc[2] = e;
    }
    __syncthreads();

    const int row = blockIdx.x * 256 + tid;
    if (row >= N) return;

    // ---- load observation ----
    float xv[OBS];
#pragma unroll
    for (int i = 0; i < OBS; i++) xv[i] = x[row * OBS + i];

    float h1[HID];

    // ================= ACTOR =================
    // layer 1 (fully unrolled, h1 in registers)
#pragma unroll
    for (int j = 0; j < HID; j++) h1[j] = sAb1[j];
#pragma unroll
    for (int i = 0; i < OBS; i++) {
        const float v = xv[i];
#pragma unroll
        for (int j = 0; j < HID; j += 4) {
            const float4 w = *(const float4*)&sAW1[i * HID + j];
            h1[j]     += v * w.x;
            h1[j + 1] += v * w.y;
            h1[j + 2] += v * w.z;
            h1[j + 3] += v * w.w;
        }
    }
#pragma unroll
    for (int j = 0; j < HID; j++) h1[j] = tanhf(h1[j]);

    // layer 2 + layer 3 fused (h2 never stored)
    float mean0 = sAb3[0], mean1 = sAb3[1], mean2 = sAb3[2], mean3 = sAb3[3];
#pragma unroll 1
    for (int j = 0; j < HID; j += 4) {
        float a0 = sAb2[j], a1 = sAb2[j + 1], a2 = sAb2[j + 2], a3 = sAb2[j + 3];
#pragma unroll
        for (int i = 0; i < HID; i++) {
            const float4 w = *(const float4*)&sAW2[i * HID + j];
            const float hv = h1[i];
            a0 += hv * w.x; a1 += hv * w.y; a2 += hv * w.z; a3 += hv * w.w;
        }
        a0 = tanhf(a0); a1 = tanhf(a1); a2 = tanhf(a2); a3 = tanhf(a3);
        const float4 w0 = *(const float4*)&sAW3[(j + 0) * ACT];
        const float4 w1 = *(const float4*)&sAW3[(j + 1) * ACT];
        const float4 w2 = *(const float4*)&sAW3[(j + 2) * ACT];
        const float4 w3 = *(const float4*)&sAW3[(j + 3) * ACT];
        mean0 += a0 * w0.x + a1 * w1.x + a2 * w2.x + a3 * w3.x;
        mean1 += a0 * w0.y + a1 * w1.y + a2 * w2.y + a3 * w3.y;
        mean2 += a0 * w0.z + a1 * w1.z + a2 * w2.z + a3 * w3.z;
        mean3 += a0 * w0.w + a1 * w1.w + a2 * w2.w + a3 * w3.w;
    }

    // ================= CRITIC =================
#pragma unroll
    for (int j = 0; j < HID; j++) h1[j] = sCb1[j];
#pragma unroll
    for (int i = 0; i < OBS; i++) {
        const float v = xv[i];
#pragma unroll
        for (int j = 0; j < HID; j += 4) {
            const float4 w = *(const float4*)&sCW1[i * HID + j];
            h1[j]     += v * w.x;
            h1[j + 1] += v * w.y;
            h1[j + 2] += v * w.z;
            h1[j + 3] += v * w.w;
        }
    }
#pragma unroll
    for (int j = 0; j < HID; j++) h1[j] = tanhf(h1[j]);

    float value = sMisc[0];
#pragma unroll 1
    for (int j = 0; j < HID; j += 4) {
        float a0 = sCb2[j], a1 = sCb2[j + 1], a2 = sCb2[j + 2], a3 = sCb2[j + 3];
#pragma unroll
        for (int i = 0; i < HID; i++) {
            const float4 w = *(const float4*)&sCW2[i * HID + j];
            const float hv = h1[i];
            a0 += hv * w.x; a1 += hv * w.y; a2 += hv * w.z; a3 += hv * w.w;
        }
        a0 = tanhf(a0); a1 = tanhf(a1); a2 = tanhf(a2); a3 = tanhf(a3);
        value += a0 * sCW3[j] + a1 * sCW3[j + 1] + a2 * sCW3[j + 2] + a3 * sCW3[j + 3];
    }

    // ================= CBF-QP =================
    float G0 = 0.f, G1 = 0.f, G2 = 0.f, G3 = 0.f, gf = 0.f;
#pragma unroll
    for (int s = 0; s < OBS; s++) {
        const float gr = grads[row * OBS + s];
        const float4 gx = *(const float4*)&g_x[row * OBS * ACT + s * ACT];
        G0 -= gr * gx.x; G1 -= gr * gx.y; G2 -= gr * gx.z; G3 -= gr * gx.w;
        gf += gr * f_x[row * OBS + s];
    }
    const float4 av = *(const float4*)&action[row * ACT];
    const float h = sMisc[1] + sdfs[row] + gf
                  - (G0 * av.x + G1 * av.y + G2 * av.z + G3 * av.w);
    const float v0 = sQinv[0]  * G0 + sQinv[1]  * G1 + sQinv[2]  * G2 + sQinv[3]  * G3;
    const float v1 = sQinv[4]  * G0 + sQinv[5]  * G1 + sQinv[6]  * G2 + sQinv[7]  * G3;
    const float v2 = sQinv[8]  * G0 + sQinv[9]  * G1 + sQinv[10] * G2 + sQinv[11] * G3;
    const float v3 = sQinv[12] * G0 + sQinv[13] * G1 + sQinv[14] * G2 + sQinv[15] * G3;
    const float denom = G0 * v0 + G1 * v1 + G2 * v2 + G3 * v3;
    const float lam = fmaxf(0.0f, -h / denom);

    const float u0 = mean0 - lam * v0;
    const float u1 = mean1 - lam * v1;
    const float u2 = mean2 - lam * v2;
    const float u3 = mean3 - lam * v3;

    // ---- log-prob ----
    float z0 = (av.x - mean0) * sInvStd[0];
    float z1 = (av.y - mean1) * sInvStd[1];
    float z2 = (av.z - mean2) * sInvStd[2];
    float z3 = (av.w - mean3) * sInvStd[3];
    float lp = -0.5f * (z0 * z0 + z1 * z1 + z2 * z2 + z3 * z3)
               - (sLogstd[0] + sLogstd[1] + sLogstd[2] + sLogstd[3])
               - 2.0f * LOG_2PI;

    // ---- outputs: [u_out (N,4) | log_prob (N) | entropy (N) | value (N)] ----
    *(float4*)&out[row * 4] = make_float4(u0, u1, u2, u3);
    out[4 * N + row] = lp;
    out[5 * N + row] = sMisc[2];
    out[6 * N + row] = value;
}

extern "C" void kernel_launch(void* const* d_in, const int* in_sizes, int n_in,
                              void* d_out, int out_size) {
    const float* x      = (const float*)d_in[0];
    const float* sdfs   = (const float*)d_in[1];
    const float* grads  = (const float*)d_in[2];
    const float* f_x    = (const float*)d_in[3];
    const float* g_x    = (const float*)d_in[4];
    const float* action = (const float*)d_in[5];
    const float* cW1 = (const float*)d_in[6];
    const float* cb1 = (const float*)d_in[7];
    const float* cW2 = (const float*)d_in[8];
    const float* cb2 = (const float*)d_in[9];
    const float* cW3 = (const float*)d_in[10];
    const float* cb3 = (const float*)d_in[11];
    const float* aW1 = (const float*)d_in[12];
    const float* ab1 = (const float*)d_in[13];
    const float* aW2 = (const float*)d_in[14];
    const float* ab2 = (const float*)d_in[15];
    const float* aW3 = (const float*)d_in[16];
    const float* ab3 = (const float*)d_in[17];
    const float* logstd = (const float*)d_in[18];
    const float* L      = (const float*)d_in[19];
    const float* s0     = (const float*)d_in[20];

    const int N = in_sizes[0] / OBS;
    float* out = (float*)d_out;

    qinv_kernel<<<1, 32>>>(L);
    const int threads = 256;
    const int blocks = (N + threads - 1) / threads;
    fused_kernel<<<blocks, threads>>>(x, sdfs, grads, f_x, g_x, action,
                                      cW1, cb1, cW2, cb2, cW3, cb3,
                                      aW1, ab1, aW2, ab2, aW3, ab3,
                                      logstd, s0, out, N);
}

// round 2
// speedup vs baseline: 1.1153x; 1.1153x over previous
#include <cuda_runtime.h>
#include <math.h>

#define OBS 17
#define ACT 4
#define HID 64
#define LOG_2PI 1.8378770664093453f
#define TPB 96

__device__ float g_Qinv[16];

__device__ __forceinline__ float tanh_fast(float v) {
    float r;
    asm("tanh.approx.f32 %0, %1;" : "=f"(r) : "f"(v));
    return r;
}

// ---------------------------------------------------------------------------
// Prep: compute Qinv = (tril(L) tril(L)^T + 1e-4 I)^{-1} once, in double.
// ---------------------------------------------------------------------------
__global__ void qinv_kernel(const float* __restrict__ L) {
    if (threadIdx.x != 0 || blockIdx.x != 0) return;
    double Lt[4][4];
    for (int i = 0; i < 4; i++)
        for (int j = 0; j < 4; j++)
            Lt[i][j] = (j <= i) ? (double)L[i * 4 + j] : 0.0;
    double M[4][8];
    for (int i = 0; i < 4; i++) {
        for (int j = 0; j < 4; j++) {
            double s = (i == j) ? 1e-4 : 0.0;
            for (int k = 0; k < 4; k++) s += Lt[i][k] * Lt[j][k];
            M[i][j] = s;
            M[i][4 + j] = (i == j) ? 1.0 : 0.0;
        }
    }
    for (int c = 0; c < 4; c++) {
        int p = c;
        for (int r = c + 1; r < 4; r++) if (fabs(M[r][c]) > fabs(M[p][c])) p = r;
        if (p != c) for (int j = 0; j < 8; j++) { double t = M[c][j]; M[c][j] = M[p][j]; M[p][j] = t; }
        double inv = 1.0 / M[c][c];
        for (int j = 0; j < 8; j++) M[c][j] *= inv;
        for (int r = 0; r < 4; r++) if (r != c) {
            double f = M[r][c];
            for (int j = 0; j < 8; j++) M[r][j] -= f * M[c][j];
        }
    }
    for (int i = 0; i < 4; i++)
        for (int j = 0; j < 4; j++)
            g_Qinv[i * 4 + j] = (float)M[i][4 + j];
}

// ---------------------------------------------------------------------------
// Main fused kernel: one thread per row, 96-thread blocks, 5 blocks/SM.
// ---------------------------------------------------------------------------
__global__ __launch_bounds__(TPB, 5) void fused_kernel(
    const float* __restrict__ x, const float* __restrict__ sdfs,
    const float* __restrict__ grads, const float* __restrict__ f_x,
    const float* __restrict__ g_x, const float* __restrict__ action,
    const float* __restrict__ cW1, const float* __restrict__ cb1,
    const float* __restrict__ cW2, const float* __restrict__ cb2,
    const float* __restrict__ cW3, const float* __restrict__ cb3,
    const float* __restrict__ aW1, const float* __restrict__ ab1,
    const float* __restrict__ aW2, const float* __restrict__ ab2,
    const float* __restrict__ aW3, const float* __restrict__ ab3,
    const float* __restrict__ logstd, const float* __restrict__ s0,
    float* __restrict__ out, int N)
{
    __shared__ __align__(16) float sAW1[OBS * HID];
    __shared__ __align__(16) float sAW2[HID * HID];
    __shared__ __align__(16) float sAW3[HID * ACT];
    __shared__ __align__(16) float sCW1[OBS * HID];
    __shared__ __align__(16) float sCW2[HID * HID];
    __shared__ __align__(16) float sCW3[HID];
    __shared__ __align__(16) float sAb1[HID], sAb2[HID], sCb1[HID], sCb2[HID];
    __shared__ __align__(16) float sAb3[ACT], sLogstd[ACT], sInvStd[ACT];
    __shared__ __align__(16) float sQinv[16];
    __shared__ __align__(16) float sMisc[4]; // 0: cb3, 1: s0, 2: entropy

    const int tid = threadIdx.x;
    for (int i = tid; i < OBS * HID; i += TPB) { sAW1[i] = aW1[i]; sCW1[i] = cW1[i]; }
    for (int i = tid; i < HID * HID; i += TPB) { sAW2[i] = aW2[i]; sCW2[i] = cW2[i]; }
    for (int i = tid; i < HID * ACT; i += TPB) sAW3[i] = aW3[i];
    if (tid < HID) {
        sAb1[tid] = ab1[tid]; sAb2[tid] = ab2[tid];
        sCb1[tid] = cb1[tid]; sCb2[tid] = cb2[tid];
        sCW3[tid] = cW3[tid];
    }
    if (tid < ACT) {
        float ls = logstd[tid];
        sAb3[tid] = ab3[tid];
        sLogstd[tid] = ls;
        sInvStd[tid] = expf(-ls);
    }
    if (tid < 16) sQinv[tid] = g_Qinv[tid];
    if (tid == 0) {
        sMisc[0] = cb3[0];
        sMisc[1] = s0[0];
        float e = 0.0f;
        for (int a = 0; a < ACT; a++) e += 0.5f + 0.5f * LOG_2PI + logstd[a];
        sMisc[2] = e;
    }
    __syncthreads();

    const int row = blockIdx.x * TPB + tid;
    if (row >= N) return;

    // ---- load observation ----
    float xv[OBS];
#pragma unroll
    for (int i = 0; i < OBS; i++) xv[i] = x[row * OBS + i];

    float h1[HID];

    // ================= ACTOR =================
#pragma unroll
    for (int j = 0; j < HID; j++) h1[j] = sAb1[j];
#pragma unroll
    for (int i = 0; i < OBS; i++) {
        const float v = xv[i];
#pragma unroll
        for (int j = 0; j < HID; j += 4) {
            const float4 w = *(const float4*)&sAW1[i * HID + j];
            h1[j]     += v * w.x;
            h1[j + 1] += v * w.y;
            h1[j + 2] += v * w.z;
            h1[j + 3] += v * w.w;
        }
    }
#pragma unroll
    for (int j = 0; j < HID; j++) h1[j] = tanh_fast(h1[j]);

    // layer 2 + layer 3 fused (h2 never stored); dual accumulator chains
    float mean0 = sAb3[0], mean1 = sAb3[1], mean2 = sAb3[2], mean3 = sAb3[3];
#pragma unroll 1
    for (int j = 0; j < HID; j += 4) {
        float a0 = sAb2[j], a1 = sAb2[j + 1], a2 = sAb2[j + 2], a3 = sAb2[j + 3];
        float b0 = 0.f, b1 = 0.f, b2 = 0.f, b3 = 0.f;
#pragma unroll
        for (int i = 0; i < HID; i += 2) {
            const float4 wA = *(const float4*)&sAW2[i * HID + j];
            const float4 wB = *(const float4*)&sAW2[(i + 1) * HID + j];
            const float hA = h1[i], hB = h1[i + 1];
            a0 += hA * wA.x; a1 += hA * wA.y; a2 += hA * wA.z; a3 += hA * wA.w;
            b0 += hB * wB.x; b1 += hB * wB.y; b2 += hB * wB.z; b3 += hB * wB.w;
        }
        a0 = tanh_fast(a0 + b0); a1 = tanh_fast(a1 + b1);
        a2 = tanh_fast(a2 + b2); a3 = tanh_fast(a3 + b3);
        const float4 w0 = *(const float4*)&sAW3[(j + 0) * ACT];
        const float4 w1 = *(const float4*)&sAW3[(j + 1) * ACT];
        const float4 w2 = *(const float4*)&sAW3[(j + 2) * ACT];
        const float4 w3 = *(const float4*)&sAW3[(j + 3) * ACT];
        mean0 += a0 * w0.x + a1 * w1.x + a2 * w2.x + a3 * w3.x;
        mean1 += a0 * w0.y + a1 * w1.y + a2 * w2.y + a3 * w3.y;
        mean2 += a0 * w0.z + a1 * w1.z + a2 * w2.z + a3 * w3.z;
        mean3 += a0 * w0.w + a1 * w1.w + a2 * w2.w + a3 * w3.w;
    }

    // ================= CRITIC =================
#pragma unroll
    for (int j = 0; j < HID; j++) h1[j] = sCb1[j];
#pragma unroll
    for (int i = 0; i < OBS; i++) {
        const float v = xv[i];
#pragma unroll
        for (int j = 0; j < HID; j += 4) {
            const float4 w = *(const float4*)&sCW1[i * HID + j];
            h1[j]     += v * w.x;
            h1[j + 1] += v * w.y;
            h1[j + 2] += v * w.z;
            h1[j + 3] += v * w.w;
        }
    }
#pragma unroll
    for (int j = 0; j < HID; j++) h1[j] = tanh_fast(h1[j]);

    float value = sMisc[0];
#pragma unroll 1
    for (int j = 0; j < HID; j += 4) {
        float a0 = sCb2[j], a1 = sCb2[j + 1], a2 = sCb2[j + 2], a3 = sCb2[j + 3];
        float b0 = 0.f, b1 = 0.f, b2 = 0.f, b3 = 0.f;
#pragma unroll
        for (int i = 0; i < HID; i += 2) {
            const float4 wA = *(const float4*)&sCW2[i * HID + j];
            const float4 wB = *(const float4*)&sCW2[(i + 1) * HID + j];
            const float hA = h1[i], hB = h1[i + 1];
            a0 += hA * wA.x; a1 += hA * wA.y; a2 += hA * wA.z; a3 += hA * wA.w;
            b0 += hB * wB.x; b1 += hB * wB.y; b2 += hB * wB.z; b3 += hB * wB.w;
        }
        a0 = tanh_fast(a0 + b0); a1 = tanh_fast(a1 + b1);
        a2 = tanh_fast(a2 + b2); a3 = tanh_fast(a3 + b3);
        value += a0 * sCW3[j] + a1 * sCW3[j + 1] + a2 * sCW3[j + 2] + a3 * sCW3[j + 3];
    }

    // ================= CBF-QP =================
    float G0 = 0.f, G1 = 0.f, G2 = 0.f, G3 = 0.f, gf = 0.f;
#pragma unroll
    for (int s = 0; s < OBS; s++) {
        const float gr = grads[row * OBS + s];
        const float4 gx = *(const float4*)&g_x[row * OBS * ACT + s * ACT];
        G0 -= gr * gx.x; G1 -= gr * gx.y; G2 -= gr * gx.z; G3 -= gr * gx.w;
        gf += gr * f_x[row * OBS + s];
    }
    const float4 av = *(const float4*)&action[row * ACT];
    const float h = sMisc[1] + sdfs[row] + gf
                  - (G0 * av.x + G1 * av.y + G2 * av.z + G3 * av.w);
    const float v0 = sQinv[0]  * G0 + sQinv[1]  * G1 + sQinv[2]  * G2 + sQinv[3]  * G3;
    const float v1 = sQinv[4]  * G0 + sQinv[5]  * G1 + sQinv[6]  * G2 + sQinv[7]  * G3;
    const float v2 = sQinv[8]  * G0 + sQinv[9]  * G1 + sQinv[10] * G2 + sQinv[11] * G3;
    const float v3 = sQinv[12] * G0 + sQinv[13] * G1 + sQinv[14] * G2 + sQinv[15] * G3;
    const float denom = G0 * v0 + G1 * v1 + G2 * v2 + G3 * v3;
    const float lam = fmaxf(0.0f, -h / denom);

    const float u0 = mean0 - lam * v0;
    const float u1 = mean1 - lam * v1;
    const float u2 = mean2 - lam * v2;
    const float u3 = mean3 - lam * v3;

    // ---- log-prob ----
    float z0 = (av.x - mean0) * sInvStd[0];
    float z1 = (av.y - mean1) * sInvStd[1];
    float z2 = (av.z - mean2) * sInvStd[2];
    float z3 = (av.w - mean3) * sInvStd[3];
    float lp = -0.5f * (z0 * z0 + z1 * z1 + z2 * z2 + z3 * z3)
               - (sLogstd[0] + sLogstd[1] + sLogstd[2] + sLogstd[3])
               - 2.0f * LOG_2PI;

    // ---- outputs: [u_out (N,4) | log_prob (N) | entropy (N) | value (N)] ----
    *(float4*)&out[row * 4] = make_float4(u0, u1, u2, u3);
    out[4 * N + row] = lp;
    out[5 * N + row] = sMisc[2];
    out[6 * N + row] = value;
}

extern "C" void kernel_launch(void* const* d_in, const int* in_sizes, int n_in,
                              void* d_out, int out_size) {
    const float* x      = (const float*)d_in[0];
    const float* sdfs   = (const float*)d_in[1];
    const float* grads  = (const float*)d_in[2];
    const float* f_x    = (const float*)d_in[3];
    const float* g_x    = (const float*)d_in[4];
    const float* action = (const float*)d_in[5];
    const float* cW1 = (const float*)d_in[6];
    const float* cb1 = (const float*)d_in[7];
    const float* cW2 = (const float*)d_in[8];
    const float* cb2 = (const float*)d_in[9];
    const float* cW3 = (const float*)d_in[10];
    const float* cb3 = (const float*)d_in[11];
    const float* aW1 = (const float*)d_in[12];
    const float* ab1 = (const float*)d_in[13];
    const float* aW2 = (const float*)d_in[14];
    const float* ab2 = (const float*)d_in[15];
    const float* aW3 = (const float*)d_in[16];
    const float* ab3 = (const float*)d_in[17];
    const float* logstd = (const float*)d_in[18];
    const float* L      = (const float*)d_in[19];
    const float* s0     = (const float*)d_in[20];

    const int N = in_sizes[0] / OBS;
    float* out = (float*)d_out;

    qinv_kernel<<<1, 32>>>(L);
    const int blocks = (N + TPB - 1) / TPB;
    fused_kernel<<<blocks, TPB>>>(x, sdfs, grads, f_x, g_x, action,
                                  cW1, cb1, cW2, cb2, cW3, cb3,
                                  aW1, ab1, aW2, ab2, aW3, ab3,
                                  logstd, s0, out, N);
}